// round 3
// baseline (speedup 1.0000x reference)
#include <cuda_runtime.h>
#include <math.h>

// Problem constants
#define DIM    1024
#define BATCH  1024
#define KSET   128
#define N_MEM  100000

// ---------------- device scratch (no allocations allowed) ----------------
__device__ float g_part[2 * BATCH * DIM];  // split-K partials (8 MB)
__device__ float g_h[BATCH * DIM];         // hidden after GELU (4 MB)
__device__ float g_q[BATCH * DIM];         // queries (4 MB)

// =========================================================================
// SGEMM NT, fp32: C_part[z] = A[M,K] * B[N,K]^T over K-half z.
// BM=BN=128, BK=16, 256 threads, TM=TN=8, double-buffered smem,
// tiles stored K-major-transposed in smem for conflict-light frag loads.
// =========================================================================
template<bool USE_GH>
__global__ __launch_bounds__(256, 2)
void sgemm_nt_ksplit(const float* __restrict__ Ain,
                     const float* __restrict__ Bin)
{
    const int Kd = DIM;
    const float* A = USE_GH ? (const float*)g_h : Ain;

    const int k0 = blockIdx.z * 512;
    const int bm = blockIdx.y * 128;
    const int bn = blockIdx.x * 128;

    __shared__ float As[2][16][128];
    __shared__ float Bs[2][16][128];

    const int tid = threadIdx.x;          // 0..255
    const int lr  = tid >> 2;             // load row 0..63
    const int lc  = (tid & 3) << 2;       // load col {0,4,8,12}
    const int tx  = tid & 15;             // 0..15
    const int ty  = tid >> 4;             // 0..15

    const float* Ap = A   + (size_t)(bm + lr) * Kd + k0 + lc;
    const float* Bp = Bin + (size_t)(bn + lr) * Kd + k0 + lc;

    float acc[8][8];
#pragma unroll
    for (int i = 0; i < 8; i++)
#pragma unroll
        for (int j = 0; j < 8; j++) acc[i][j] = 0.f;

    float4 a0 = *(const float4*)(Ap);
    float4 a1 = *(const float4*)(Ap + 64 * Kd);
    float4 b0 = *(const float4*)(Bp);
    float4 b1 = *(const float4*)(Bp + 64 * Kd);

#define STORE_TILE(BUF)                                                     \
    do {                                                                    \
        As[BUF][lc+0][lr]    = a0.x; As[BUF][lc+1][lr]    = a0.y;           \
        As[BUF][lc+2][lr]    = a0.z; As[BUF][lc+3][lr]    = a0.w;           \
        As[BUF][lc+0][lr+64] = a1.x; As[BUF][lc+1][lr+64] = a1.y;           \
        As[BUF][lc+2][lr+64] = a1.z; As[BUF][lc+3][lr+64] = a1.w;           \
        Bs[BUF][lc+0][lr]    = b0.x; Bs[BUF][lc+1][lr]    = b0.y;           \
        Bs[BUF][lc+2][lr]    = b0.z; Bs[BUF][lc+3][lr]    = b0.w;           \
        Bs[BUF][lc+0][lr+64] = b1.x; Bs[BUF][lc+1][lr+64] = b1.y;           \
        Bs[BUF][lc+2][lr+64] = b1.z; Bs[BUF][lc+3][lr+64] = b1.w;           \
    } while (0)

    STORE_TILE(0);
    __syncthreads();

    int buf = 0;
#pragma unroll 1
    for (int kt = 0; kt < 512; kt += 16) {
        const bool more = (kt + 16) < 512;
        if (more) {
            a0 = *(const float4*)(Ap + kt + 16);
            a1 = *(const float4*)(Ap + kt + 16 + 64 * Kd);
            b0 = *(const float4*)(Bp + kt + 16);
            b1 = *(const float4*)(Bp + kt + 16 + 64 * Kd);
        }
#pragma unroll
        for (int kk = 0; kk < 16; kk++) {
            float a[8], bb[8];
            *(float4*)(a)      = *(const float4*)&As[buf][kk][ty * 8];
            *(float4*)(a + 4)  = *(const float4*)&As[buf][kk][ty * 8 + 4];
            *(float4*)(bb)     = *(const float4*)&Bs[buf][kk][tx * 8];
            *(float4*)(bb + 4) = *(const float4*)&Bs[buf][kk][tx * 8 + 4];
#pragma unroll
            for (int i = 0; i < 8; i++)
#pragma unroll
                for (int j = 0; j < 8; j++)
                    acc[i][j] = fmaf(a[i], bb[j], acc[i][j]);
        }
        if (more) {
            buf ^= 1;
            STORE_TILE(buf);
            __syncthreads();
        }
    }
#undef STORE_TILE

    float* C = g_part + (size_t)blockIdx.z * (BATCH * DIM);
#pragma unroll
    for (int i = 0; i < 8; i++) {
        const int r = bm + ty * 8 + i;
        float4 v0 = make_float4(acc[i][0], acc[i][1], acc[i][2], acc[i][3]);
        float4 v1 = make_float4(acc[i][4], acc[i][5], acc[i][6], acc[i][7]);
        *(float4*)(C + (size_t)r * DIM + bn + tx * 8)     = v0;
        *(float4*)(C + (size_t)r * DIM + bn + tx * 8 + 4) = v1;
    }
}

// =========================================================================
// Epilogue: sum split-K partials + bias (+ exact GELU for layer 1)
// =========================================================================
__device__ __forceinline__ float gelu_exact(float x) {
    return 0.5f * x * (1.0f + erff(x * 0.70710678118654752f));
}

template<bool GELU>
__global__ __launch_bounds__(256)
void epilogue_k(const float* __restrict__ bias)
{
    const int i = blockIdx.x * blockDim.x + threadIdx.x;   // float4 index
    float4 p0 = ((const float4*)g_part)[i];
    float4 p1 = ((const float4*)g_part)[i + (BATCH * DIM) / 4];
    float4 bb = ((const float4*)bias)[i & 255];
    float4 v;
    v.x = p0.x + p1.x + bb.x;
    v.y = p0.y + p1.y + bb.y;
    v.z = p0.z + p1.z + bb.z;
    v.w = p0.w + p1.w + bb.w;
    if (GELU) {
        v.x = gelu_exact(v.x); v.y = gelu_exact(v.y);
        v.z = gelu_exact(v.z); v.w = gelu_exact(v.w);
    }
    float* dst = GELU ? g_h : g_q;
    ((float4*)dst)[i] = v;
}

// =========================================================================
// Fused gather + scores + softmax + recombine (single HBM pass per row).
// One block per batch row b. 8 warps, each owns 16 keys with a private
// online-softmax state (m, s, y[1024] in registers); merged via smem.
// NOTE: Kset arrives as int32 (JAX x64 disabled downgrades int64->int32).
// =========================================================================
__global__ __launch_bounds__(256)
void attn_kernel(const float* __restrict__ mem,
                 const int* __restrict__ kset,
                 float* __restrict__ p_out,
                 float* __restrict__ y_out)
{
    const int b    = blockIdx.x;
    const int tid  = threadIdx.x;
    const int w    = tid >> 5;
    const int lane = tid & 31;

    __shared__ float s_scores[KSET];
    __shared__ float s_m[8];
    __shared__ float s_s[8];
    __shared__ float s_y[8][DIM];   // 32 KB

    // query row in registers: element layout (lane + 32*j) per float4 slot
    const float4* qv = (const float4*)(g_q + (size_t)b * DIM);
    float4 qr[8];
#pragma unroll
    for (int j = 0; j < 8; j++) qr[j] = qv[lane + 32 * j];

    float m = -INFINITY, s = 0.f;
    float4 y[8];
#pragma unroll
    for (int j = 0; j < 8; j++) y[j] = make_float4(0.f, 0.f, 0.f, 0.f);

    const int* krow = kset + (size_t)b * KSET;

#pragma unroll 1
    for (int i = 0; i < 16; i++) {
        const int k = w * 16 + i;
        int idx = krow[k];
        // defensive clamp: turns any dtype/range surprise into a finite
        // result instead of an illegal access (2 ALU ops vs 4KB HBM read)
        idx = min(max(idx, 0), N_MEM - 1);
        const float4* rv = (const float4*)(mem + (size_t)idx * DIM);

        float4 r[8];
#pragma unroll
        for (int j = 0; j < 8; j++) r[j] = rv[lane + 32 * j];

        float part = 0.f;
#pragma unroll
        for (int j = 0; j < 8; j++) {
            part = fmaf(r[j].x, qr[j].x, part);
            part = fmaf(r[j].y, qr[j].y, part);
            part = fmaf(r[j].z, qr[j].z, part);
            part = fmaf(r[j].w, qr[j].w, part);
        }
#pragma unroll
        for (int o = 16; o > 0; o >>= 1)
            part += __shfl_xor_sync(0xFFFFFFFFu, part, o);
        // 'part' = full score on all lanes

        if (lane == 0) s_scores[k] = part;

        const float mn    = fmaxf(m, part);
        const float scale = __expf(m - mn);      // 0 on first iteration (m=-inf)
        const float e     = __expf(part - mn);
        s = s * scale + e;
#pragma unroll
        for (int j = 0; j < 8; j++) {
            y[j].x = fmaf(y[j].x, scale, e * r[j].x);
            y[j].y = fmaf(y[j].y, scale, e * r[j].y);
            y[j].z = fmaf(y[j].z, scale, e * r[j].z);
            y[j].w = fmaf(y[j].w, scale, e * r[j].w);
        }
        m = mn;
    }

    if (lane == 0) { s_m[w] = m; s_s[w] = s; }
    __syncthreads();

    // global max / sum over the 8 warp-local states (all threads redundantly)
    float M = -INFINITY;
#pragma unroll
    for (int w2 = 0; w2 < 8; w2++) M = fmaxf(M, s_m[w2]);
    float S = 0.f;
#pragma unroll
    for (int w2 = 0; w2 < 8; w2++) S += s_s[w2] * __expf(s_m[w2] - M);
    const float invS = 1.f / S;

    // rescale warp-local accumulator into smem slab
    const float f = __expf(m - M);
    float4* ys = (float4*)s_y[w];
#pragma unroll
    for (int j = 0; j < 8; j++) {
        float4 v = y[j];
        v.x *= f; v.y *= f; v.z *= f; v.w *= f;
        ys[lane + 32 * j] = v;
    }
    __syncthreads();

    // cross-warp reduction: thread tid owns float4 group 'tid'
    {
        float4 acc = make_float4(0.f, 0.f, 0.f, 0.f);
#pragma unroll
        for (int w2 = 0; w2 < 8; w2++) {
            float4 v = ((const float4*)s_y[w2])[tid];
            acc.x += v.x; acc.y += v.y; acc.z += v.z; acc.w += v.w;
        }
        acc.x *= invS; acc.y *= invS; acc.z *= invS; acc.w *= invS;
        ((float4*)(y_out + (size_t)b * DIM))[tid] = acc;
    }

    if (tid < KSET)
        p_out[(size_t)b * KSET + tid] = __expf(s_scores[tid] - M) * invS;
}

// =========================================================================
// Launch: GEMM1 -> epilogue(GELU) -> GEMM2 -> epilogue -> fused attention
// Output layout: P0 [B,K] flattened first, then Y0 [B,D].
// =========================================================================
extern "C" void kernel_launch(void* const* d_in, const int* in_sizes, int n_in,
                              void* d_out, int out_size)
{
    const float* emb  = (const float*)d_in[0];
    const float* mem  = (const float*)d_in[1];
    const int*   kset = (const int*)d_in[2];
    const float* W1   = (const float*)d_in[3];
    const float* b1   = (const float*)d_in[4];
    const float* W2   = (const float*)d_in[5];
    const float* b2   = (const float*)d_in[6];

    float* out   = (float*)d_out;
    float* p_out = out;                    // [B, K]
    float* y_out = out + BATCH * KSET;     // [B, D]

    dim3 ggrid(8, 8, 2);

    sgemm_nt_ksplit<false><<<ggrid, 256>>>(emb, W1);
    epilogue_k<true><<<(BATCH * DIM) / 4 / 256, 256>>>(b1);
    sgemm_nt_ksplit<true><<<ggrid, 256>>>(nullptr, W2);
    epilogue_k<false><<<(BATCH * DIM) / 4 / 256, 256>>>(b2);
    attn_kernel<<<BATCH, 256>>>(mem, kset, p_out, y_out);
}